// round 9
// baseline (speedup 1.0000x reference)
#include <cuda_runtime.h>
#include <cuda_bf16.h>
#include <math.h>
#include <stdint.h>

// ---------------- problem constants ----------------
#define N_ROWS     8192
#define DIM        256
#define NUM_PIDS   5532
#define NUM_CQ     5000
#define L_TOT      (NUM_PIDS + NUM_CQ)   // 10532
#define IGNORE_IDX 5554
#define OIM_SCALAR 30.0f

// ---------------- tiling ----------------
#define BM 128
#define BN 128
#define BK 32
#define NSTAGE 4
#define NCB ((L_TOT + BN - 1) / BN)      // 83 column blocks
#define NRB (N_ROWS / BM)                // 64 row blocks
#define B_PAD (NCB * BN)                 // 10624 padded bank rows
#define ASTRIDE 40                       // bf16 elems per smem row (32 + 8 pad)

// dynamic smem layout (bytes)
#define STAGE_BYTES (BM * ASTRIDE * 2)          // 10240
#define OFF_SMA  0
#define OFF_SMB  (NSTAGE * STAGE_BYTES)         // 40960
#define OFF_REL  (2 * NSTAGE * STAGE_BYTES)     // 81920
#define OFF_LBL  (OFF_REL + BN * 4)             // 82432
#define OFF_RED  (OFF_LBL + BM * 4)             // 82944
#define SMEM_TOTAL (OFF_RED + BM * 4 * 4)       // 84992

// ---------------- device scratch (zero-initialized globals) ----------------
__device__ __nv_bfloat16 g_Abf[N_ROWS * DIM];
__device__ __nv_bfloat16 g_Bbf[B_PAD * DIM];   // rows >= L_TOT stay 0 forever
__device__ float g_partial[NCB][N_ROWS];
__device__ float g_labellogit[N_ROWS];
__device__ float g_bsum[NRB];
__device__ float g_bcnt[NRB];
__device__ unsigned int g_rowticket[NRB];      // all start 0, self-reset
__device__ unsigned int g_ticket;              // starts 0, self-reset

// ---------------- PTX helpers (sm_80+, valid under compute_100) ----------
__device__ __forceinline__ uint32_t smem_u32(const void* p) {
    uint32_t a;
    asm("{ .reg .u64 t; cvta.to.shared.u64 t, %1; cvt.u32.u64 %0, t; }"
        : "=r"(a) : "l"(p));
    return a;
}
__device__ __forceinline__ void cp_async16(uint32_t dst, const void* src) {
    asm volatile("cp.async.cg.shared.global [%0], [%1], 16;"
                 :: "r"(dst), "l"(src) : "memory");
}
__device__ __forceinline__ void cp_commit() {
    asm volatile("cp.async.commit_group;" ::: "memory");
}
template <int N>
__device__ __forceinline__ void cp_wait() {
    asm volatile("cp.async.wait_group %0;" :: "n"(N) : "memory");
}
__device__ __forceinline__ void ldsm_x4(uint32_t* r, uint32_t addr) {
    asm volatile("ldmatrix.sync.aligned.m8n8.x4.shared.b16 {%0,%1,%2,%3}, [%4];"
                 : "=r"(r[0]), "=r"(r[1]), "=r"(r[2]), "=r"(r[3]) : "r"(addr));
}
__device__ __forceinline__ void mma16816(float* d, const uint32_t* a, const uint32_t* b) {
    asm volatile(
        "mma.sync.aligned.m16n8k16.row.col.f32.bf16.bf16.f32 "
        "{%0,%1,%2,%3}, {%4,%5,%6,%7}, {%8,%9}, {%0,%1,%2,%3};"
        : "+f"(d[0]), "+f"(d[1]), "+f"(d[2]), "+f"(d[3])
        : "r"(a[0]), "r"(a[1]), "r"(a[2]), "r"(a[3]), "r"(b[0]), "r"(b[1]));
}

// ---------------------------------------------------------------------------
// Kernel 0: fp32 -> bf16 conversion, 2 independent float4 chunks per thread
// ---------------------------------------------------------------------------
#define A_F4   (N_ROWS * DIM / 4)          // 524288
#define LUT_F4 (NUM_PIDS * DIM / 4)        // 354048
#define CQ_F4  (NUM_CQ * DIM / 4)          // 320000
#define TOT_F4 (A_F4 + LUT_F4 + CQ_F4)     // 1198336
#define HALF_F4 (TOT_F4 / 2)               // 599168

__device__ __forceinline__ void cvt_one(int i, const float* A,
                                        const float* lut, const float* cq) {
    const float4* src;
    __nv_bfloat16* dst;
    if (i < A_F4) {
        src = (const float4*)A + i;
        dst = g_Abf + (size_t)i * 4;
    } else if (i < A_F4 + LUT_F4) {
        int j = i - A_F4;
        src = (const float4*)lut + j;
        dst = g_Bbf + (size_t)j * 4;
    } else {
        int j = i - A_F4 - LUT_F4;
        src = (const float4*)cq + j;
        dst = g_Bbf + (size_t)(LUT_F4 + j) * 4;
    }
    float4 v = *src;
    ushort4 o;
    o.x = __bfloat16_as_ushort(__float2bfloat16_rn(v.x));
    o.y = __bfloat16_as_ushort(__float2bfloat16_rn(v.y));
    o.z = __bfloat16_as_ushort(__float2bfloat16_rn(v.z));
    o.w = __bfloat16_as_ushort(__float2bfloat16_rn(v.w));
    *reinterpret_cast<ushort4*>(dst) = o;
}

__global__ void cvt_kernel(const float* __restrict__ A,
                           const float* __restrict__ lut,
                           const float* __restrict__ cq) {
    int i = blockIdx.x * blockDim.x + threadIdx.x;
    if (i >= HALF_F4) return;
    cvt_one(i, A, lut, cq);
    cvt_one(i + HALF_F4, A, lut, cq);
}

// ---------------------------------------------------------------------------
// Kernel 1: mma.sync bf16 GEMM + fused exp-rowsum + fused loss reduction
// ---------------------------------------------------------------------------
__global__ __launch_bounds__(256, 2)
void oim_mma_kernel(const float* __restrict__ rel, const int* __restrict__ label,
                    float* __restrict__ out)
{
    extern __shared__ __align__(16) char smem[];
    float* relS = (float*)(smem + OFF_REL);
    int*   lblS = (int*)(smem + OFF_LBL);
    float* red  = (float*)(smem + OFF_RED);

    __shared__ unsigned int s_last;
    __shared__ float wsum2[8], wcnt2[8];

    const int tid = threadIdx.x;
    const int wid = tid >> 5;
    const int lane = tid & 31;
    const int warp_row = wid >> 2;        // 0..1
    const int warp_col = wid & 3;         // 0..3
    const int g = lane >> 2;
    const int t = lane & 3;

    const int bn = blockIdx.x;            // 0..82
    const int bm = blockIdx.y;            // 0..63
    const int row0 = bm * BM;
    const int col0 = bn * BN;

    if (tid < BN) {
        int c = col0 + tid;
        relS[tid] = (c < L_TOT) ? rel[c] * OIM_SCALAR : 0.0f;
    }
    if (tid < BM) lblS[tid] = label[row0 + tid];

    const uint32_t smA_u = smem_u32(smem + OFF_SMA);
    const uint32_t smB_u = smem_u32(smem + OFF_SMB);

    const int c0i = tid, c1i = tid + 256;
    const int m0 = c0i >> 2, ko0 = (c0i & 3) * 8;
    const int m1 = c1i >> 2, ko1 = (c1i & 3) * 8;
    const uint32_t dstA0 = smA_u + (uint32_t)(m0 * ASTRIDE + ko0) * 2;
    const uint32_t dstA1 = smA_u + (uint32_t)(m1 * ASTRIDE + ko1) * 2;
    const uint32_t dstB0 = smB_u + (uint32_t)(m0 * ASTRIDE + ko0) * 2;
    const uint32_t dstB1 = smB_u + (uint32_t)(m1 * ASTRIDE + ko1) * 2;
    const __nv_bfloat16* srcA0 = g_Abf + (size_t)(row0 + m0) * DIM + ko0;
    const __nv_bfloat16* srcA1 = g_Abf + (size_t)(row0 + m1) * DIM + ko1;
    const __nv_bfloat16* srcB0 = g_Bbf + (size_t)(col0 + m0) * DIM + ko0;
    const __nv_bfloat16* srcB1 = g_Bbf + (size_t)(col0 + m1) * DIM + ko1;

    // A ldmatrix x4: row = warp_row*64 + (lane&15), kofs = (lane>>4)*8
    const uint32_t aOff = smA_u +
        (uint32_t)(((warp_row * 64 + (lane & 15)) * ASTRIDE) + ((lane >> 4) << 3)) * 2;
    // B ldmatrix x4 (two n8 blocks per load): row = warp_col*32 + (lane&7) + ((lane&16)>>1),
    // kofs = ((lane>>3)&1)*8   (verified numerically in R5)
    const uint32_t bOff = smB_u +
        (uint32_t)(((warp_col * 32 + (lane & 7) + ((lane & 16) >> 1)) * ASTRIDE)
                   + (((lane >> 3) & 1) << 3)) * 2;

    float acc[4][4][4];
#pragma unroll
    for (int mi = 0; mi < 4; mi++)
#pragma unroll
        for (int ni = 0; ni < 4; ni++)
#pragma unroll
            for (int h = 0; h < 4; h++)
                acc[mi][ni][h] = 0.0f;

    // prologue: prefetch stages 0..2
#pragma unroll
    for (int s = 0; s < NSTAGE - 1; s++) {
        const uint32_t so = (uint32_t)s * STAGE_BYTES;
        const int gko = s * BK;
        cp_async16(dstA0 + so, srcA0 + gko);
        cp_async16(dstA1 + so, srcA1 + gko);
        cp_async16(dstB0 + so, srcB0 + gko);
        cp_async16(dstB1 + so, srcB1 + gko);
        cp_commit();
    }

#pragma unroll
    for (int kc = 0; kc < 8; kc++) {
        if (kc <= 5)      cp_wait<2>();
        else if (kc == 6) cp_wait<1>();
        else              cp_wait<0>();
        __syncthreads();

        if (kc < 5) {
            const uint32_t so = (uint32_t)((kc + 3) & (NSTAGE - 1)) * STAGE_BYTES;
            const int gko = (kc + 3) * BK;
            cp_async16(dstA0 + so, srcA0 + gko);
            cp_async16(dstA1 + so, srcA1 + gko);
            cp_async16(dstB0 + so, srcB0 + gko);
            cp_async16(dstB1 + so, srcB1 + gko);
            cp_commit();
        }

        const uint32_t so = (uint32_t)(kc & (NSTAGE - 1)) * STAGE_BYTES;
        const uint32_t aBase = aOff + so;
        const uint32_t bBase = bOff + so;
#pragma unroll
        for (int ks = 0; ks < 2; ks++) {
            uint32_t a[4][4], b[4][2];
#pragma unroll
            for (int mi = 0; mi < 4; mi++)
                ldsm_x4(a[mi], aBase + (uint32_t)(mi * 16 * ASTRIDE + ks * 16) * 2);
#pragma unroll
            for (int nj = 0; nj < 2; nj++) {
                uint32_t r[4];
                ldsm_x4(r, bBase + (uint32_t)(nj * 16 * ASTRIDE + ks * 16) * 2);
                b[nj * 2][0] = r[0]; b[nj * 2][1] = r[1];
                b[nj * 2 + 1][0] = r[2]; b[nj * 2 + 1][1] = r[3];
            }
#pragma unroll
            for (int mi = 0; mi < 4; mi++)
#pragma unroll
                for (int ni = 0; ni < 4; ni++)
                    mma16816(acc[mi][ni], a[mi], b[ni]);
        }
    }

    // ---- fused epilogue: exp row-sums + label logit capture ----
#pragma unroll
    for (int mi = 0; mi < 4; mi++) {
        const int rl0 = warp_row * 64 + mi * 16 + g;
        const int rl1 = rl0 + 8;
        const int lbl0 = lblS[rl0];
        const int lbl1 = lblS[rl1];
        float s0 = 0.0f, s1 = 0.0f;
#pragma unroll
        for (int ni = 0; ni < 4; ni++) {
#pragma unroll
            for (int h = 0; h < 2; h++) {
                const int lc = warp_col * 32 + ni * 8 + t * 2 + h;
                const int c = col0 + lc;
                const float rs = relS[lc];
                const float l0 = acc[mi][ni][h] * rs;
                const float l1 = acc[mi][ni][2 + h] * rs;
                if (c < L_TOT) {
                    s0 += __expf(l0);
                    s1 += __expf(l1);
                }
                if (c == lbl0) g_labellogit[row0 + rl0] = l0;   // unique writer
                if (c == lbl1) g_labellogit[row0 + rl1] = l1;
            }
        }
        s0 += __shfl_xor_sync(0xFFFFFFFFu, s0, 1);
        s0 += __shfl_xor_sync(0xFFFFFFFFu, s0, 2);
        s1 += __shfl_xor_sync(0xFFFFFFFFu, s1, 1);
        s1 += __shfl_xor_sync(0xFFFFFFFFu, s1, 2);
        if (t == 0) {
            red[rl0 * 4 + warp_col] = s0;
            red[rl1 * 4 + warp_col] = s1;
        }
    }
    __syncthreads();
    if (tid < BM) {
        float s = red[tid * 4 + 0] + red[tid * 4 + 1]
                + red[tid * 4 + 2] + red[tid * 4 + 3];
        g_partial[bn][row0 + tid] = s;
    }

    // ---- fused loss tail: 83rd CTA of this row block computes row losses ----
    __threadfence();
    __syncthreads();
    if (tid == 0) {
        unsigned int d = atomicAdd(&g_rowticket[bm], 1u);
        if (d == NCB - 1) {
            s_last = 1u;
            g_rowticket[bm] = 0u;              // self-reset for next replay
        } else {
            s_last = 0u;
        }
    }
    __syncthreads();
    if (s_last) {
        __threadfence();                       // acquire other CTAs' writes
        float loss = 0.0f, cnt = 0.0f;
        if (tid < BM) {
            const int row = row0 + tid;
            float s = 0.0f;
#pragma unroll 4
            for (int b = 0; b < NCB; b++)
                s += __ldcg(&g_partial[b][row]);
            const int lbl = lblS[tid];
            const bool valid = (lbl != IGNORE_IDX);
            const float ll = __ldcg(&g_labellogit[row]);
            loss = valid ? (logf(s) - ll) : 0.0f;
            cnt  = valid ? 1.0f : 0.0f;
        }
#pragma unroll
        for (int off = 16; off > 0; off >>= 1) {
            loss += __shfl_down_sync(0xFFFFFFFFu, loss, off);
            cnt  += __shfl_down_sync(0xFFFFFFFFu, cnt, off);
        }
        if (lane == 0) { wsum2[wid] = loss; wcnt2[wid] = cnt; }
        __syncthreads();
        if (tid == 0) {
            float bs = 0.0f, bc = 0.0f;
#pragma unroll
            for (int k = 0; k < 8; k++) { bs += wsum2[k]; bc += wcnt2[k]; }
            g_bsum[bm] = bs;
            g_bcnt[bm] = bc;
            __threadfence();
            unsigned int tk = atomicAdd(&g_ticket, 1u);
            s_last = (tk == NRB - 1) ? 2u : 0u;
        }
        __syncthreads();
        if (s_last == 2u && tid < 32) {
            __threadfence();
            float fs = __ldcg(&g_bsum[tid]) + __ldcg(&g_bsum[tid + 32]);
            float fc = __ldcg(&g_bcnt[tid]) + __ldcg(&g_bcnt[tid + 32]);
#pragma unroll
            for (int off = 16; off > 0; off >>= 1) {
                fs += __shfl_down_sync(0xFFFFFFFFu, fs, off);
                fc += __shfl_down_sync(0xFFFFFFFFu, fc, off);
            }
            if (tid == 0) {
                out[0] = fs / fmaxf(fc, 1.0f);
                g_ticket = 0u;                 // self-reset for next replay
            }
        }
    }
}

// ---------------------------------------------------------------------------
extern "C" void kernel_launch(void* const* d_in, const int* in_sizes, int n_in,
                              void* d_out, int out_size) {
    const float* inputs = (const float*)d_in[0];   // [8192, 256]
    const int*   label  = (const int*)  d_in[1];   // [8192]
    const float* lut    = (const float*)d_in[3];   // [5532, 256]
    const float* cq     = (const float*)d_in[4];   // [5000, 256]
    const float* rel    = (const float*)d_in[5];   // [10532]
    float* out = (float*)d_out;

    static bool attr_set = false;
    if (!attr_set) {
        cudaFuncSetAttribute(oim_mma_kernel,
                             cudaFuncAttributeMaxDynamicSharedMemorySize, SMEM_TOTAL);
        attr_set = true;
    }

    cvt_kernel<<<(HALF_F4 + 255) / 256, 256>>>(inputs, lut, cq);

    dim3 grid(NCB, N_ROWS / BM);   // 83 x 64
    oim_mma_kernel<<<grid, 256, SMEM_TOTAL>>>(rel, label, out);
}

// round 10
// speedup vs baseline: 1.0153x; 1.0153x over previous
#include <cuda_runtime.h>
#include <cuda_bf16.h>
#include <math.h>
#include <stdint.h>

// ---------------- problem constants ----------------
#define N_ROWS     8192
#define DIM        256
#define NUM_PIDS   5532
#define NUM_CQ     5000
#define L_TOT      (NUM_PIDS + NUM_CQ)   // 10532
#define IGNORE_IDX 5554
#define OIM_SCALAR 30.0f

// ---------------- tiling ----------------
#define BM 128
#define BN 64
#define BK 32
#define NSTAGE 4
#define NCB ((L_TOT + BN - 1) / BN)      // 165 column blocks
#define NRB (N_ROWS / BM)                // 64 row blocks
#define B_PAD (NCB * BN)                 // 10560 padded bank rows
#define ASTRIDE 40                       // bf16 elems per smem row (32 + 8 pad)

// dynamic smem layout (bytes)
#define STAGE_A (BM * ASTRIDE * 2)              // 10240
#define STAGE_B (BN * ASTRIDE * 2)              // 5120
#define OFF_SMA  0
#define OFF_SMB  (NSTAGE * STAGE_A)             // 40960
#define OFF_REL  (OFF_SMB + NSTAGE * STAGE_B)   // 61440
#define OFF_LBL  (OFF_REL + BN * 4)             // 61696
#define OFF_RED  (OFF_LBL + BM * 4)             // 62208
#define SMEM_TOTAL (OFF_RED + BM * 2 * 4)       // 63232

// ---------------- device scratch (zero-initialized globals) ----------------
__device__ __nv_bfloat16 g_Abf[N_ROWS * DIM];
__device__ __nv_bfloat16 g_Bbf[B_PAD * DIM];   // rows >= L_TOT stay 0 forever
__device__ float g_partial[NCB][N_ROWS];
__device__ float g_labellogit[N_ROWS];
__device__ float g_bsum[32];
__device__ float g_bcnt[32];
__device__ unsigned int g_ticket;              // starts 0, reset by last block

// ---------------- PTX helpers (sm_80+, valid under compute_100) ----------
__device__ __forceinline__ uint32_t smem_u32(const void* p) {
    uint32_t a;
    asm("{ .reg .u64 t; cvta.to.shared.u64 t, %1; cvt.u32.u64 %0, t; }"
        : "=r"(a) : "l"(p));
    return a;
}
__device__ __forceinline__ void cp_async16(uint32_t dst, const void* src) {
    asm volatile("cp.async.cg.shared.global [%0], [%1], 16;"
                 :: "r"(dst), "l"(src) : "memory");
}
__device__ __forceinline__ void cp_commit() {
    asm volatile("cp.async.commit_group;" ::: "memory");
}
template <int N>
__device__ __forceinline__ void cp_wait() {
    asm volatile("cp.async.wait_group %0;" :: "n"(N) : "memory");
}
__device__ __forceinline__ void ldsm_x4(uint32_t* r, uint32_t addr) {
    asm volatile("ldmatrix.sync.aligned.m8n8.x4.shared.b16 {%0,%1,%2,%3}, [%4];"
                 : "=r"(r[0]), "=r"(r[1]), "=r"(r[2]), "=r"(r[3]) : "r"(addr));
}
__device__ __forceinline__ void mma16816(float* d, const uint32_t* a, const uint32_t* b) {
    asm volatile(
        "mma.sync.aligned.m16n8k16.row.col.f32.bf16.bf16.f32 "
        "{%0,%1,%2,%3}, {%4,%5,%6,%7}, {%8,%9}, {%0,%1,%2,%3};"
        : "+f"(d[0]), "+f"(d[1]), "+f"(d[2]), "+f"(d[3])
        : "r"(a[0]), "r"(a[1]), "r"(a[2]), "r"(a[3]), "r"(b[0]), "r"(b[1]));
}

// ---------------------------------------------------------------------------
// Kernel 0: fp32 -> bf16 conversion, 2 independent float4 chunks per thread
// ---------------------------------------------------------------------------
#define A_F4   (N_ROWS * DIM / 4)          // 524288
#define LUT_F4 (NUM_PIDS * DIM / 4)        // 354048
#define CQ_F4  (NUM_CQ * DIM / 4)          // 320000
#define TOT_F4 (A_F4 + LUT_F4 + CQ_F4)     // 1198336
#define HALF_F4 (TOT_F4 / 2)               // 599168

__device__ __forceinline__ void cvt_one(int i, const float* A,
                                        const float* lut, const float* cq) {
    const float4* src;
    __nv_bfloat16* dst;
    if (i < A_F4) {
        src = (const float4*)A + i;
        dst = g_Abf + (size_t)i * 4;
    } else if (i < A_F4 + LUT_F4) {
        int j = i - A_F4;
        src = (const float4*)lut + j;
        dst = g_Bbf + (size_t)j * 4;
    } else {
        int j = i - A_F4 - LUT_F4;
        src = (const float4*)cq + j;
        dst = g_Bbf + (size_t)(LUT_F4 + j) * 4;
    }
    float4 v = *src;
    ushort4 o;
    o.x = __bfloat16_as_ushort(__float2bfloat16_rn(v.x));
    o.y = __bfloat16_as_ushort(__float2bfloat16_rn(v.y));
    o.z = __bfloat16_as_ushort(__float2bfloat16_rn(v.z));
    o.w = __bfloat16_as_ushort(__float2bfloat16_rn(v.w));
    *reinterpret_cast<ushort4*>(dst) = o;
}

__global__ void cvt_kernel(const float* __restrict__ A,
                           const float* __restrict__ lut,
                           const float* __restrict__ cq) {
    int i = blockIdx.x * blockDim.x + threadIdx.x;
    if (i >= HALF_F4) return;
    cvt_one(i, A, lut, cq);
    cvt_one(i + HALF_F4, A, lut, cq);
}

// ---------------------------------------------------------------------------
// Kernel 1: mma.sync bf16 GEMM, CTA 128x64, warp tile 32x32, 3 CTAs/SM
// ---------------------------------------------------------------------------
__global__ __launch_bounds__(256, 3)
void oim_mma_kernel(const float* __restrict__ rel, const int* __restrict__ label)
{
    extern __shared__ __align__(16) char smem[];
    float* relS = (float*)(smem + OFF_REL);
    int*   lblS = (int*)(smem + OFF_LBL);
    float* red  = (float*)(smem + OFF_RED);

    const int tid = threadIdx.x;
    const int wid = tid >> 5;
    const int lane = tid & 31;
    const int warp_row = wid >> 1;        // 0..3 -> 32 rows each
    const int warp_col = wid & 1;         // 0..1 -> 32 cols each
    const int g = lane >> 2;              // 0..7
    const int t = lane & 3;               // 0..3

    const int bn = blockIdx.x;            // 0..164
    const int bm = blockIdx.y;            // 0..63
    const int row0 = bm * BM;
    const int col0 = bn * BN;

    if (tid < BN) {
        int c = col0 + tid;
        relS[tid] = (c < L_TOT) ? rel[c] * OIM_SCALAR : 0.0f;
    }
    if (tid < BM) lblS[tid] = label[row0 + tid];

    const uint32_t smA_u = smem_u32(smem + OFF_SMA);
    const uint32_t smB_u = smem_u32(smem + OFF_SMB);

    // global->shared: A = 512 chunks of 16B (2/thread), B = 256 chunks (1/thread)
    const int cA0 = tid, cA1 = tid + 256, cB = tid;
    const int ma0 = cA0 >> 2, koa0 = (cA0 & 3) * 8;
    const int ma1 = cA1 >> 2, koa1 = (cA1 & 3) * 8;
    const int mb  = cB >> 2,  kob  = (cB & 3) * 8;
    const uint32_t dstA0 = smA_u + (uint32_t)(ma0 * ASTRIDE + koa0) * 2;
    const uint32_t dstA1 = smA_u + (uint32_t)(ma1 * ASTRIDE + koa1) * 2;
    const uint32_t dstB0 = smB_u + (uint32_t)(mb * ASTRIDE + kob) * 2;
    const __nv_bfloat16* srcA0 = g_Abf + (size_t)(row0 + ma0) * DIM + koa0;
    const __nv_bfloat16* srcA1 = g_Abf + (size_t)(row0 + ma1) * DIM + koa1;
    const __nv_bfloat16* srcB0 = g_Bbf + (size_t)(col0 + mb) * DIM + kob;

    // A ldmatrix x4 (m16 x k16): row = warp_row*32 + (lane&15), kofs = (lane>>4)*8
    const uint32_t aOff = smA_u +
        (uint32_t)(((warp_row * 32 + (lane & 15)) * ASTRIDE) + ((lane >> 4) << 3)) * 2;
    // B ldmatrix x4 (two n8 blocks): row = warp_col*32 + (lane&7) + ((lane&16)>>1),
    // kofs = ((lane>>3)&1)*8   (verified numerically in R5/R9)
    const uint32_t bOff = smB_u +
        (uint32_t)(((warp_col * 32 + (lane & 7) + ((lane & 16) >> 1)) * ASTRIDE)
                   + (((lane >> 3) & 1) << 3)) * 2;

    float acc[2][4][4];
#pragma unroll
    for (int mi = 0; mi < 2; mi++)
#pragma unroll
        for (int ni = 0; ni < 4; ni++)
#pragma unroll
            for (int h = 0; h < 4; h++)
                acc[mi][ni][h] = 0.0f;

    // prologue: prefetch stages 0..2
#pragma unroll
    for (int s = 0; s < NSTAGE - 1; s++) {
        const int gko = s * BK;
        cp_async16(dstA0 + (uint32_t)s * STAGE_A, srcA0 + gko);
        cp_async16(dstA1 + (uint32_t)s * STAGE_A, srcA1 + gko);
        cp_async16(dstB0 + (uint32_t)s * STAGE_B, srcB0 + gko);
        cp_commit();
    }

#pragma unroll
    for (int kc = 0; kc < 8; kc++) {
        if (kc <= 5)      cp_wait<2>();
        else if (kc == 6) cp_wait<1>();
        else              cp_wait<0>();
        __syncthreads();

        if (kc < 5) {
            const int st = (kc + 3) & (NSTAGE - 1);
            const int gko = (kc + 3) * BK;
            cp_async16(dstA0 + (uint32_t)st * STAGE_A, srcA0 + gko);
            cp_async16(dstA1 + (uint32_t)st * STAGE_A, srcA1 + gko);
            cp_async16(dstB0 + (uint32_t)st * STAGE_B, srcB0 + gko);
            cp_commit();
        }

        const int cur = kc & (NSTAGE - 1);
        const uint32_t aBase = aOff + (uint32_t)cur * STAGE_A;
        const uint32_t bBase = bOff + (uint32_t)cur * STAGE_B;
#pragma unroll
        for (int ks = 0; ks < 2; ks++) {
            uint32_t a[2][4], b[4][2];
#pragma unroll
            for (int mi = 0; mi < 2; mi++)
                ldsm_x4(a[mi], aBase + (uint32_t)(mi * 16 * ASTRIDE + ks * 16) * 2);
#pragma unroll
            for (int nj = 0; nj < 2; nj++) {
                uint32_t r[4];
                ldsm_x4(r, bBase + (uint32_t)(nj * 16 * ASTRIDE + ks * 16) * 2);
                b[nj * 2][0] = r[0]; b[nj * 2][1] = r[1];
                b[nj * 2 + 1][0] = r[2]; b[nj * 2 + 1][1] = r[3];
            }
#pragma unroll
            for (int mi = 0; mi < 2; mi++)
#pragma unroll
                for (int ni = 0; ni < 4; ni++)
                    mma16816(acc[mi][ni], a[mi], b[ni]);
        }
    }

    // ---- fused epilogue: exp row-sums + label logit capture ----
#pragma unroll
    for (int mi = 0; mi < 2; mi++) {
        const int rl0 = warp_row * 32 + mi * 16 + g;
        const int rl1 = rl0 + 8;
        const int lbl0 = lblS[rl0];
        const int lbl1 = lblS[rl1];
        float s0 = 0.0f, s1 = 0.0f;
#pragma unroll
        for (int ni = 0; ni < 4; ni++) {
#pragma unroll
            for (int h = 0; h < 2; h++) {
                const int lc = warp_col * 32 + ni * 8 + t * 2 + h;
                const int c = col0 + lc;
                const float rs = relS[lc];
                const float l0 = acc[mi][ni][h] * rs;
                const float l1 = acc[mi][ni][2 + h] * rs;
                if (c < L_TOT) {
                    s0 += __expf(l0);
                    s1 += __expf(l1);
                }
                if (c == lbl0) g_labellogit[row0 + rl0] = l0;   // unique writer
                if (c == lbl1) g_labellogit[row0 + rl1] = l1;
            }
        }
        s0 += __shfl_xor_sync(0xFFFFFFFFu, s0, 1);
        s0 += __shfl_xor_sync(0xFFFFFFFFu, s0, 2);
        s1 += __shfl_xor_sync(0xFFFFFFFFu, s1, 1);
        s1 += __shfl_xor_sync(0xFFFFFFFFu, s1, 2);
        if (t == 0) {
            red[rl0 * 2 + warp_col] = s0;
            red[rl1 * 2 + warp_col] = s1;
        }
    }
    __syncthreads();
    if (tid < BM) {
        g_partial[bn][row0 + tid] = red[tid * 2 + 0] + red[tid * 2 + 1];
    }
}

// ---------------------------------------------------------------------------
// Kernel 2: per-row loss + block reduction + last-block final reduce
// ---------------------------------------------------------------------------
__global__ __launch_bounds__(256)
void oim_rowloss_kernel(const int* __restrict__ label, float* __restrict__ out) {
    __shared__ float wsum[8], wcnt[8];
    __shared__ unsigned int is_last;
    const int i = blockIdx.x * 256 + threadIdx.x;    // row id, 32*256 = 8192
    float s = 0.0f;
#pragma unroll 5
    for (int b = 0; b < NCB; b++)
        s += g_partial[b][i];
    const int lbl = label[i];
    const bool valid = (lbl != IGNORE_IDX);
    float loss = valid ? (logf(s) - g_labellogit[i]) : 0.0f;
    float cnt  = valid ? 1.0f : 0.0f;
#pragma unroll
    for (int off = 16; off > 0; off >>= 1) {
        loss += __shfl_down_sync(0xFFFFFFFFu, loss, off);
        cnt  += __shfl_down_sync(0xFFFFFFFFu, cnt, off);
    }
    const int lane = threadIdx.x & 31;
    const int w = threadIdx.x >> 5;
    if (lane == 0) { wsum[w] = loss; wcnt[w] = cnt; }
    __syncthreads();
    if (threadIdx.x == 0) {
        float bs = 0.0f, bc = 0.0f;
#pragma unroll
        for (int k = 0; k < 8; k++) { bs += wsum[k]; bc += wcnt[k]; }
        g_bsum[blockIdx.x] = bs;
        g_bcnt[blockIdx.x] = bc;
        __threadfence();
        unsigned int tk = atomicAdd(&g_ticket, 1u);
        is_last = (tk == 31u) ? 1u : 0u;
    }
    __syncthreads();
    if (is_last && threadIdx.x < 32) {
        __threadfence();
        float fs = ((volatile float*)g_bsum)[threadIdx.x];
        float fc = ((volatile float*)g_bcnt)[threadIdx.x];
#pragma unroll
        for (int off = 16; off > 0; off >>= 1) {
            fs += __shfl_down_sync(0xFFFFFFFFu, fs, off);
            fc += __shfl_down_sync(0xFFFFFFFFu, fc, off);
        }
        if (threadIdx.x == 0) {
            out[0] = fs / fmaxf(fc, 1.0f);
            g_ticket = 0u;              // reset for next replay
        }
    }
}

// ---------------------------------------------------------------------------
extern "C" void kernel_launch(void* const* d_in, const int* in_sizes, int n_in,
                              void* d_out, int out_size) {
    const float* inputs = (const float*)d_in[0];   // [8192, 256]
    const int*   label  = (const int*)  d_in[1];   // [8192]
    const float* lut    = (const float*)d_in[3];   // [5532, 256]
    const float* cq     = (const float*)d_in[4];   // [5000, 256]
    const float* rel    = (const float*)d_in[5];   // [10532]
    float* out = (float*)d_out;

    static bool attr_set = false;
    if (!attr_set) {
        cudaFuncSetAttribute(oim_mma_kernel,
                             cudaFuncAttributeMaxDynamicSharedMemorySize, SMEM_TOTAL);
        attr_set = true;
    }

    cvt_kernel<<<(HALF_F4 + 255) / 256, 256>>>(inputs, lut, cq);

    dim3 grid(NCB, N_ROWS / BM);   // 165 x 64
    oim_mma_kernel<<<grid, 256, SMEM_TOTAL>>>(rel, label);

    oim_rowloss_kernel<<<32, 256>>>(label, out);
}

// round 11
// speedup vs baseline: 1.0966x; 1.0801x over previous
#include <cuda_runtime.h>
#include <cuda_bf16.h>
#include <math.h>
#include <stdint.h>

// ---------------- problem constants ----------------
#define N_ROWS     8192
#define DIM        256
#define NUM_PIDS   5532
#define NUM_CQ     5000
#define L_TOT      (NUM_PIDS + NUM_CQ)   // 10532
#define IGNORE_IDX 5554
#define OIM_SCALAR 30.0f

// ---------------- tiling ----------------
#define BM 128
#define BN 128
#define BK 32
#define NSTAGE 4
#define NCB ((L_TOT + BN - 1) / BN)      // 83 column blocks
#define B_PAD (NCB * BN)                 // 10624 padded bank rows
#define ASTRIDE 40                       // bf16 elems per smem row (32 + 8 pad)

// dynamic smem layout (bytes)
#define STAGE_BYTES (BM * ASTRIDE * 2)          // 10240
#define OFF_SMA  0
#define OFF_SMB  (NSTAGE * STAGE_BYTES)         // 40960
#define OFF_REL  (2 * NSTAGE * STAGE_BYTES)     // 81920
#define OFF_LBL  (OFF_REL + BN * 4)             // 82432
#define OFF_RED  (OFF_LBL + BM * 4)             // 82944
#define SMEM_TOTAL (OFF_RED + BM * 4 * 4)       // 84992

// ---------------- device scratch (zero-initialized globals) ----------------
__device__ __nv_bfloat16 g_Abf[N_ROWS * DIM];
__device__ __nv_bfloat16 g_Bbf[B_PAD * DIM];   // rows >= L_TOT stay 0 forever
__device__ float g_partial[NCB][N_ROWS];
__device__ float g_labellogit[N_ROWS];
__device__ float g_bsum[32];
__device__ float g_bcnt[32];
__device__ unsigned int g_ticket;              // starts 0, reset by last block

// ---------------- PTX helpers (sm_80+, valid under compute_100) ----------
__device__ __forceinline__ uint32_t smem_u32(const void* p) {
    uint32_t a;
    asm("{ .reg .u64 t; cvta.to.shared.u64 t, %1; cvt.u32.u64 %0, t; }"
        : "=r"(a) : "l"(p));
    return a;
}
__device__ __forceinline__ void cp_async16(uint32_t dst, const void* src) {
    asm volatile("cp.async.cg.shared.global [%0], [%1], 16;"
                 :: "r"(dst), "l"(src) : "memory");
}
__device__ __forceinline__ void cp_commit() {
    asm volatile("cp.async.commit_group;" ::: "memory");
}
template <int N>
__device__ __forceinline__ void cp_wait() {
    asm volatile("cp.async.wait_group %0;" :: "n"(N) : "memory");
}
__device__ __forceinline__ void ldsm_x4(uint32_t* r, uint32_t addr) {
    asm volatile("ldmatrix.sync.aligned.m8n8.x4.shared.b16 {%0,%1,%2,%3}, [%4];"
                 : "=r"(r[0]), "=r"(r[1]), "=r"(r[2]), "=r"(r[3]) : "r"(addr));
}
__device__ __forceinline__ void mma16816(float* d, const uint32_t* a, const uint32_t* b) {
    asm volatile(
        "mma.sync.aligned.m16n8k16.row.col.f32.bf16.bf16.f32 "
        "{%0,%1,%2,%3}, {%4,%5,%6,%7}, {%8,%9}, {%0,%1,%2,%3};"
        : "+f"(d[0]), "+f"(d[1]), "+f"(d[2]), "+f"(d[3])
        : "r"(a[0]), "r"(a[1]), "r"(a[2]), "r"(a[3]), "r"(b[0]), "r"(b[1]));
}

// ---------------------------------------------------------------------------
// Kernel 0: fp32 -> bf16 conversion, 4 independent float4 chunks per thread
// ---------------------------------------------------------------------------
#define A_F4   (N_ROWS * DIM / 4)          // 524288
#define LUT_F4 (NUM_PIDS * DIM / 4)        // 354048
#define CQ_F4  (NUM_CQ * DIM / 4)          // 320000
#define TOT_F4 (A_F4 + LUT_F4 + CQ_F4)     // 1198336
#define QTR_F4 (TOT_F4 / 4)                // 299584

__device__ __forceinline__ void cvt_one(int i, const float* A,
                                        const float* lut, const float* cq) {
    const float4* src;
    __nv_bfloat16* dst;
    if (i < A_F4) {
        src = (const float4*)A + i;
        dst = g_Abf + (size_t)i * 4;
    } else if (i < A_F4 + LUT_F4) {
        int j = i - A_F4;
        src = (const float4*)lut + j;
        dst = g_Bbf + (size_t)j * 4;
    } else {
        int j = i - A_F4 - LUT_F4;
        src = (const float4*)cq + j;
        dst = g_Bbf + (size_t)(LUT_F4 + j) * 4;
    }
    float4 v = *src;
    ushort4 o;
    o.x = __bfloat16_as_ushort(__float2bfloat16_rn(v.x));
    o.y = __bfloat16_as_ushort(__float2bfloat16_rn(v.y));
    o.z = __bfloat16_as_ushort(__float2bfloat16_rn(v.z));
    o.w = __bfloat16_as_ushort(__float2bfloat16_rn(v.w));
    *reinterpret_cast<ushort4*>(dst) = o;
}

__global__ void cvt_kernel(const float* __restrict__ A,
                           const float* __restrict__ lut,
                           const float* __restrict__ cq) {
    int i = blockIdx.x * blockDim.x + threadIdx.x;
    if (i >= QTR_F4) return;
    cvt_one(i, A, lut, cq);
    cvt_one(i + QTR_F4, A, lut, cq);
    cvt_one(i + 2 * QTR_F4, A, lut, cq);
    cvt_one(i + 3 * QTR_F4, A, lut, cq);
}

// ---------------------------------------------------------------------------
// Kernel 1: mma.sync bf16 GEMM, 4-stage cp.async pipeline, fused exp-rowsum
// (R4 configuration; B fragments via ldmatrix.x4)
// ---------------------------------------------------------------------------
__global__ __launch_bounds__(256)
void oim_mma_kernel(const float* __restrict__ rel, const int* __restrict__ label)
{
    extern __shared__ __align__(16) char smem[];
    float* relS = (float*)(smem + OFF_REL);
    int*   lblS = (int*)(smem + OFF_LBL);
    float* red  = (float*)(smem + OFF_RED);

    const int tid = threadIdx.x;
    const int wid = tid >> 5;
    const int lane = tid & 31;
    const int warp_row = wid >> 2;        // 0..1
    const int warp_col = wid & 3;         // 0..3
    const int g = lane >> 2;
    const int t = lane & 3;

    const int bn = blockIdx.x;            // 0..82
    const int bm = blockIdx.y;            // 0..63
    const int row0 = bm * BM;
    const int col0 = bn * BN;

    if (tid < BN) {
        int c = col0 + tid;
        relS[tid] = (c < L_TOT) ? rel[c] * OIM_SCALAR : 0.0f;
    }
    if (tid < BM) lblS[tid] = label[row0 + tid];

    const uint32_t smA_u = smem_u32(smem + OFF_SMA);
    const uint32_t smB_u = smem_u32(smem + OFF_SMB);

    const int c0i = tid, c1i = tid + 256;
    const int m0 = c0i >> 2, ko0 = (c0i & 3) * 8;
    const int m1 = c1i >> 2, ko1 = (c1i & 3) * 8;
    const uint32_t dstA0 = smA_u + (uint32_t)(m0 * ASTRIDE + ko0) * 2;
    const uint32_t dstA1 = smA_u + (uint32_t)(m1 * ASTRIDE + ko1) * 2;
    const uint32_t dstB0 = smB_u + (uint32_t)(m0 * ASTRIDE + ko0) * 2;
    const uint32_t dstB1 = smB_u + (uint32_t)(m1 * ASTRIDE + ko1) * 2;
    const __nv_bfloat16* srcA0 = g_Abf + (size_t)(row0 + m0) * DIM + ko0;
    const __nv_bfloat16* srcA1 = g_Abf + (size_t)(row0 + m1) * DIM + ko1;
    const __nv_bfloat16* srcB0 = g_Bbf + (size_t)(col0 + m0) * DIM + ko0;
    const __nv_bfloat16* srcB1 = g_Bbf + (size_t)(col0 + m1) * DIM + ko1;

    // A ldmatrix x4: row = warp_row*64 + (lane&15), kofs = (lane>>4)*8
    const uint32_t aOff = smA_u +
        (uint32_t)(((warp_row * 64 + (lane & 15)) * ASTRIDE) + ((lane >> 4) << 3)) * 2;
    // B ldmatrix x4 (two n8 blocks per load): row = warp_col*32 + (lane&7) + ((lane&16)>>1),
    // kofs = ((lane>>3)&1)*8   (mapping verified by R5/R9/R10 rel_err)
    const uint32_t bOff = smB_u +
        (uint32_t)(((warp_col * 32 + (lane & 7) + ((lane & 16) >> 1)) * ASTRIDE)
                   + (((lane >> 3) & 1) << 3)) * 2;

    float acc[4][4][4];
#pragma unroll
    for (int mi = 0; mi < 4; mi++)
#pragma unroll
        for (int ni = 0; ni < 4; ni++)
#pragma unroll
            for (int h = 0; h < 4; h++)
                acc[mi][ni][h] = 0.0f;

    // prologue: prefetch stages 0..2
#pragma unroll
    for (int s = 0; s < NSTAGE - 1; s++) {
        const uint32_t so = (uint32_t)s * STAGE_BYTES;
        const int gko = s * BK;
        cp_async16(dstA0 + so, srcA0 + gko);
        cp_async16(dstA1 + so, srcA1 + gko);
        cp_async16(dstB0 + so, srcB0 + gko);
        cp_async16(dstB1 + so, srcB1 + gko);
        cp_commit();
    }

#pragma unroll
    for (int kc = 0; kc < 8; kc++) {
        if (kc <= 5)      cp_wait<2>();
        else if (kc == 6) cp_wait<1>();
        else              cp_wait<0>();
        __syncthreads();

        if (kc < 5) {
            const uint32_t so = (uint32_t)((kc + 3) & (NSTAGE - 1)) * STAGE_BYTES;
            const int gko = (kc + 3) * BK;
            cp_async16(dstA0 + so, srcA0 + gko);
            cp_async16(dstA1 + so, srcA1 + gko);
            cp_async16(dstB0 + so, srcB0 + gko);
            cp_async16(dstB1 + so, srcB1 + gko);
            cp_commit();
        }

        const uint32_t so = (uint32_t)(kc & (NSTAGE - 1)) * STAGE_BYTES;
        const uint32_t aBase = aOff + so;
        const uint32_t bBase = bOff + so;
#pragma unroll
        for (int ks = 0; ks < 2; ks++) {
            uint32_t a[4][4], b[4][2];
#pragma unroll
            for (int mi = 0; mi < 4; mi++)
                ldsm_x4(a[mi], aBase + (uint32_t)(mi * 16 * ASTRIDE + ks * 16) * 2);
#pragma unroll
            for (int nj = 0; nj < 2; nj++) {
                uint32_t r[4];
                ldsm_x4(r, bBase + (uint32_t)(nj * 16 * ASTRIDE + ks * 16) * 2);
                b[nj * 2][0] = r[0]; b[nj * 2][1] = r[1];
                b[nj * 2 + 1][0] = r[2]; b[nj * 2 + 1][1] = r[3];
            }
#pragma unroll
            for (int mi = 0; mi < 4; mi++)
#pragma unroll
                for (int ni = 0; ni < 4; ni++)
                    mma16816(acc[mi][ni], a[mi], b[ni]);
        }
    }

    // ---- fused epilogue ----
#pragma unroll
    for (int mi = 0; mi < 4; mi++) {
        const int rl0 = warp_row * 64 + mi * 16 + g;
        const int rl1 = rl0 + 8;
        const int lbl0 = lblS[rl0];
        const int lbl1 = lblS[rl1];
        float s0 = 0.0f, s1 = 0.0f;
#pragma unroll
        for (int ni = 0; ni < 4; ni++) {
#pragma unroll
            for (int h = 0; h < 2; h++) {
                const int lc = warp_col * 32 + ni * 8 + t * 2 + h;
                const int c = col0 + lc;
                const float rs = relS[lc];
                const float l0 = acc[mi][ni][h] * rs;
                const float l1 = acc[mi][ni][2 + h] * rs;
                if (c < L_TOT) {
                    s0 += __expf(l0);
                    s1 += __expf(l1);
                }
                if (c == lbl0) g_labellogit[row0 + rl0] = l0;   // unique writer
                if (c == lbl1) g_labellogit[row0 + rl1] = l1;
            }
        }
        s0 += __shfl_xor_sync(0xFFFFFFFFu, s0, 1);
        s0 += __shfl_xor_sync(0xFFFFFFFFu, s0, 2);
        s1 += __shfl_xor_sync(0xFFFFFFFFu, s1, 1);
        s1 += __shfl_xor_sync(0xFFFFFFFFu, s1, 2);
        if (t == 0) {
            red[rl0 * 4 + warp_col] = s0;
            red[rl1 * 4 + warp_col] = s1;
        }
    }
    __syncthreads();
    if (tid < BM) {
        float s = red[tid * 4 + 0] + red[tid * 4 + 1]
                + red[tid * 4 + 2] + red[tid * 4 + 3];
        g_partial[bn][row0 + tid] = s;
    }
}

// ---------------------------------------------------------------------------
// Kernel 2: per-row loss + block reduction + last-block final reduce
// ---------------------------------------------------------------------------
__global__ __launch_bounds__(256)
void oim_rowloss_kernel(const int* __restrict__ label, float* __restrict__ out) {
    __shared__ float wsum[8], wcnt[8];
    __shared__ unsigned int is_last;
    const int i = blockIdx.x * 256 + threadIdx.x;    // row id, 32*256 = 8192
    float s = 0.0f;
#pragma unroll 4
    for (int b = 0; b < NCB; b++)
        s += g_partial[b][i];
    const int lbl = label[i];
    const bool valid = (lbl != IGNORE_IDX);
    float loss = valid ? (logf(s) - g_labellogit[i]) : 0.0f;
    float cnt  = valid ? 1.0f : 0.0f;
#pragma unroll
    for (int off = 16; off > 0; off >>= 1) {
        loss += __shfl_down_sync(0xFFFFFFFFu, loss, off);
        cnt  += __shfl_down_sync(0xFFFFFFFFu, cnt, off);
    }
    const int lane = threadIdx.x & 31;
    const int w = threadIdx.x >> 5;
    if (lane == 0) { wsum[w] = loss; wcnt[w] = cnt; }
    __syncthreads();
    if (threadIdx.x == 0) {
        float bs = 0.0f, bc = 0.0f;
#pragma unroll
        for (int k = 0; k < 8; k++) { bs += wsum[k]; bc += wcnt[k]; }
        g_bsum[blockIdx.x] = bs;
        g_bcnt[blockIdx.x] = bc;
        __threadfence();
        unsigned int tk = atomicAdd(&g_ticket, 1u);
        is_last = (tk == 31u) ? 1u : 0u;
    }
    __syncthreads();
    if (is_last && threadIdx.x < 32) {
        __threadfence();
        float fs = ((volatile float*)g_bsum)[threadIdx.x];
        float fc = ((volatile float*)g_bcnt)[threadIdx.x];
#pragma unroll
        for (int off = 16; off > 0; off >>= 1) {
            fs += __shfl_down_sync(0xFFFFFFFFu, fs, off);
            fc += __shfl_down_sync(0xFFFFFFFFu, fc, off);
        }
        if (threadIdx.x == 0) {
            out[0] = fs / fmaxf(fc, 1.0f);
            g_ticket = 0u;              // reset for next replay
        }
    }
}

// ---------------------------------------------------------------------------
extern "C" void kernel_launch(void* const* d_in, const int* in_sizes, int n_in,
                              void* d_out, int out_size) {
    const float* inputs = (const float*)d_in[0];   // [8192, 256]
    const int*   label  = (const int*)  d_in[1];   // [8192]
    const float* lut    = (const float*)d_in[3];   // [5532, 256]
    const float* cq     = (const float*)d_in[4];   // [5000, 256]
    const float* rel    = (const float*)d_in[5];   // [10532]
    float* out = (float*)d_out;

    static bool attr_set = false;
    if (!attr_set) {
        cudaFuncSetAttribute(oim_mma_kernel,
                             cudaFuncAttributeMaxDynamicSharedMemorySize, SMEM_TOTAL);
        attr_set = true;
    }

    cvt_kernel<<<(QTR_F4 + 255) / 256, 256>>>(inputs, lut, cq);

    dim3 grid(NCB, N_ROWS / BM);   // 83 x 64
    oim_mma_kernel<<<grid, 256, SMEM_TOTAL>>>(rel, label);

    oim_rowloss_kernel<<<32, 256>>>(label, out);
}